// round 2
// baseline (speedup 1.0000x reference)
#include <cuda_runtime.h>
#include <cuda_bf16.h>
#include <stdint.h>

#define DI __device__ __forceinline__

// ---------------- problem constants ----------------
static constexpr int    NDIM     = 4096;
static constexpr float  INVSCALE = 1.0f / (31.75f * 127.0f);   // 1/(sx*sw)

// ---------------- GEMM tiling ----------------
static constexpr int BM = 128, BN = 128, BK = 32;
static constexpr int STAGES = 4;
static constexpr int KT = NDIM / BK;                    // 128 k-iterations
static constexpr int A_STAGE_B = BM * BK * 2;           // 8192
static constexpr int B_STAGE_B = BN * BK * 2;           // 8192
static constexpr int STAGE_B   = A_STAGE_B + B_STAGE_B; // 16384
static constexpr int SMEM_TOTAL = STAGES * STAGE_B;     // 65536

// ---------------- device scratch (allocation-free rule) ----------------
__device__ __nv_bfloat16 g_Xq[(size_t)NDIM * NDIM];   // quantized activations (integer-valued)
__device__ __nv_bfloat16 g_Wq[(size_t)NDIM * NDIM];   // quantized weights (integer-valued)
__device__ float         g_badd[NDIM];                // epilogue bias term

// ---------------- PTX helpers ----------------
DI uint32_t smem_u32(const void* p) {
    uint32_t a;
    asm("{ .reg .u64 t; cvta.to.shared.u64 t, %1; cvt.u32.u64 %0, t; }" : "=r"(a) : "l"(p));
    return a;
}
DI void cp16(uint32_t dst, const void* src) {
    asm volatile("cp.async.cg.shared.global [%0], [%1], 16;" :: "r"(dst), "l"(src) : "memory");
}
DI void cp_commit() { asm volatile("cp.async.commit_group;" ::: "memory"); }
template <int N> DI void cp_wait() { asm volatile("cp.async.wait_group %0;" :: "n"(N) : "memory"); }

DI void ldsm4(uint32_t (&r)[4], uint32_t addr) {
    asm volatile("ldmatrix.sync.aligned.m8n8.x4.shared.b16 {%0,%1,%2,%3}, [%4];"
                 : "=r"(r[0]), "=r"(r[1]), "=r"(r[2]), "=r"(r[3]) : "r"(addr));
}
DI void mma16816(float* c, const uint32_t* a, uint32_t b0, uint32_t b1) {
    asm volatile(
        "mma.sync.aligned.m16n8k16.row.col.f32.bf16.bf16.f32 "
        "{%0,%1,%2,%3}, {%4,%5,%6,%7}, {%8,%9}, {%0,%1,%2,%3};"
        : "+f"(c[0]), "+f"(c[1]), "+f"(c[2]), "+f"(c[3])
        : "r"(a[0]), "r"(a[1]), "r"(a[2]), "r"(a[3]), "r"(b0), "r"(b1));
}

// swizzled byte offset for (row, 16B-chunk c in [0,4)) within a [rows x 32] bf16 tile
DI uint32_t sw_off(int row, int c) {
    return (uint32_t)(row * 64 + ((c ^ ((row >> 1) & 3)) << 4));
}

// ---------------- quantize kernels ----------------
__global__ void quant_kernel(const float4* __restrict__ src, int which,
                             float clip, float scale) {
    size_t i = (size_t)blockIdx.x * blockDim.x + threadIdx.x;
    float4 v = src[i];
    float a0 = rintf(fminf(clip, fmaxf(-clip, v.x)) * scale);
    float a1 = rintf(fminf(clip, fmaxf(-clip, v.y)) * scale);
    float a2 = rintf(fminf(clip, fmaxf(-clip, v.z)) * scale);
    float a3 = rintf(fminf(clip, fmaxf(-clip, v.w)) * scale);
    __nv_bfloat162 p0 = __floats2bfloat162_rn(a0, a1);
    __nv_bfloat162 p1 = __floats2bfloat162_rn(a2, a3);
    uint2 o;
    o.x = *reinterpret_cast<uint32_t*>(&p0);
    o.y = *reinterpret_cast<uint32_t*>(&p1);
    uint2* dst = reinterpret_cast<uint2*>(which ? g_Wq : g_Xq);
    dst[i] = o;
}

__global__ void quant_bias_kernel(const float* __restrict__ b) {
    int i = blockIdx.x * blockDim.x + threadIdx.x;
    float q = rintf(fminf(1.0f, fmaxf(-1.0f, b[i])) * 127.0f);
    g_badd[i] = 32.0f * q * INVSCALE;   // quantized ones-column (=32) * quantized bias
}

// ---------------- GEMM ----------------
DI void load_stage(const __nv_bfloat16* __restrict__ Ag,
                   const __nv_bfloat16* __restrict__ Bg,
                   uint32_t a_s, uint32_t b_s, int kc, int tid) {
    // A: 128 rows x 4 chunks (16B) = 512 chunks; 256 threads x 2
#pragma unroll
    for (int j = 0; j < 2; ++j) {
        int idx = tid + j * 256;
        int row = idx >> 2, c = idx & 3;
        cp16(a_s + sw_off(row, c), Ag + ((size_t)row * NDIM + kc + c * 8));
    }
#pragma unroll
    for (int j = 0; j < 2; ++j) {
        int idx = tid + j * 256;
        int row = idx >> 2, c = idx & 3;
        cp16(b_s + sw_off(row, c), Bg + ((size_t)row * NDIM + kc + c * 8));
    }
}

__global__ __launch_bounds__(256, 2)
void gemm_kernel(const float* __restrict__ noise, float* __restrict__ out) {
    extern __shared__ __align__(1024) char smem[];
    const uint32_t smem_base = smem_u32(smem);
    const int tid  = threadIdx.x;
    const int lane = tid & 31;
    const int warp = tid >> 5;
    const int warpM = warp >> 1;     // 0..3, 32 rows each
    const int warpN = warp & 1;      // 0..1, 64 cols each

    const int tileM = blockIdx.y, tileN = blockIdx.x;
    const __nv_bfloat16* Ag = g_Xq + (size_t)tileM * BM * NDIM;
    const __nv_bfloat16* Bg = g_Wq + (size_t)tileN * BN * NDIM;

    float c[2][8][4];
#pragma unroll
    for (int i = 0; i < 2; ++i)
#pragma unroll
        for (int j = 0; j < 8; ++j)
#pragma unroll
            for (int k = 0; k < 4; ++k) c[i][j][k] = 0.0f;

    // ldmatrix per-lane row / chunk-select precompute
    const int lrow  = lane & 15;     // row within 16-row matrix pair
    const int csel  = lane >> 4;     // 0: k0-7, 1: k8-15
    const int rA0 = warpM * 32 + lrow,       rA1 = rA0 + 16;
    const int rB0 = warpN * 64 + lrow;       // + p*16 for p in 0..3

    // prologue: fill STAGES-1 stages
#pragma unroll
    for (int s = 0; s < STAGES - 1; ++s) {
        uint32_t a_s = smem_base + s * STAGE_B;
        load_stage(Ag, Bg, a_s, a_s + A_STAGE_B, s * BK, tid);
        cp_commit();
    }

    for (int kt = 0; kt < KT; ++kt) {
        cp_wait<STAGES - 2>();
        __syncthreads();
        const int s = kt & (STAGES - 1);
        const uint32_t a_s = smem_base + s * STAGE_B;
        const uint32_t b_s = a_s + A_STAGE_B;

        // issue next stage's loads first (overlap with compute)
        if (kt + STAGES - 1 < KT) {
            uint32_t na = smem_base + ((kt + STAGES - 1) & (STAGES - 1)) * STAGE_B;
            load_stage(Ag, Bg, na, na + A_STAGE_B, (kt + STAGES - 1) * BK, tid);
        }
        cp_commit();

#pragma unroll
        for (int kk = 0; kk < 2; ++kk) {
            const int kb = kk * 2 + csel;
            uint32_t a0[4], a1[4], b[4][4];
            ldsm4(a0, a_s + (uint32_t)(rA0 * 64) + (uint32_t)((kb ^ ((rA0 >> 1) & 3)) << 4));
            ldsm4(a1, a_s + (uint32_t)(rA1 * 64) + (uint32_t)((kb ^ ((rA1 >> 1) & 3)) << 4));
#pragma unroll
            for (int p = 0; p < 4; ++p) {
                const int rB = rB0 + p * 16;
                ldsm4(b[p], b_s + (uint32_t)(rB * 64) + (uint32_t)((kb ^ ((rB >> 1) & 3)) << 4));
            }
#pragma unroll
            for (int p = 0; p < 4; ++p) {
                mma16816(c[0][2 * p + 0], a0, b[p][0], b[p][2]);
                mma16816(c[0][2 * p + 1], a0, b[p][1], b[p][3]);
                mma16816(c[1][2 * p + 0], a1, b[p][0], b[p][2]);
                mma16816(c[1][2 * p + 1], a1, b[p][1], b[p][3]);
            }
        }
    }

    // ---- fused epilogue: out = acc*INV + badd[n] + 0.01*noise ----
    const int mBase = tileM * BM + warpM * 32 + (lane >> 2);
    const int nBase = tileN * BN + warpN * 64 + (lane & 3) * 2;
#pragma unroll
    for (int mt = 0; mt < 2; ++mt) {
#pragma unroll
        for (int nt = 0; nt < 8; ++nt) {
#pragma unroll
            for (int half = 0; half < 2; ++half) {
                const int m = mBase + mt * 16 + half * 8;
                const int n = nBase + nt * 8;
                const size_t off = (size_t)m * NDIM + n;
                float2 nz = *reinterpret_cast<const float2*>(noise + off);
                float2 bd = *reinterpret_cast<const float2*>(g_badd + n);
                float2 o;
                o.x = fmaf(c[mt][nt][2 * half + 0], INVSCALE, fmaf(0.01f, nz.x, bd.x));
                o.y = fmaf(c[mt][nt][2 * half + 1], INVSCALE, fmaf(0.01f, nz.y, bd.y));
                *reinterpret_cast<float2*>(out + off) = o;
            }
        }
    }
}

// ---------------- launch ----------------
extern "C" void kernel_launch(void* const* d_in, const int* in_sizes, int n_in,
                              void* d_out, int out_size) {
    const float* x  = (const float*)d_in[0];   // tensor  [4096,4096]
    const float* w  = (const float*)d_in[1];   // weights [4096,4096]
    const float* b  = (const float*)d_in[2];   // biases  [4096]
    const float* nz = (const float*)d_in[3];   // noise   [4096,4096]
    float* out = (float*)d_out;

    const int qgrid = (NDIM * NDIM / 4) / 256;  // 16384
    quant_kernel<<<qgrid, 256>>>((const float4*)x, 0, 4.0f, 31.75f);
    quant_kernel<<<qgrid, 256>>>((const float4*)w, 1, 1.0f, 127.0f);
    quant_bias_kernel<<<NDIM / 256, 256>>>(b);

    cudaFuncSetAttribute(gemm_kernel, cudaFuncAttributeMaxDynamicSharedMemorySize, SMEM_TOTAL);
    dim3 grid(NDIM / BN, NDIM / BM);            // 32 x 32 = 1024 CTAs
    gemm_kernel<<<grid, 256, SMEM_TOTAL>>>(nz, out);
}